// round 15
// baseline (speedup 1.0000x reference)
#include <cuda_runtime.h>
#include <cuda_fp16.h>
#include <mma.h>

using namespace nvcuda;

#define NN 100000
#define NE 1600000
#define CH 64
#define OUTC 32
#define NB 148
#define NT 1024
#define NCSR 98                          // CSR-builder blocks; rest run GEMM1
#define CHUNKC 1021                      // ceil(NN / NCSR)
#define NTILES (NN / 16)                 // 6250 exact row tiles
#define NRW (NE + 8 * NN + 16)           // int2 edge entries, 8-padded segments

// ---------------- device scratch ----------------
__device__ int    g_deg[NN];
__device__ int    g_off[NN];
__device__ int    g_cur[NN];
__device__ float  g_dinv[NN];
__device__ int    g_bsums[NCSR];
__device__ __align__(16) int2   g_rw[NRW];      // (src_row, bits(dinv[src])) sorted by target
__device__ __align__(16) __half g_a[NN * CH];   // GEMM A operand (fp16)
__device__ __align__(16) float  g_t[NN * CH];   // GEMM output (fp32) = agg gather source
__device__ unsigned g_cnt;
__device__ unsigned g_gen;                       // monotonic barrier generation

// grid barrier across the NCSR CSR blocks only (all co-resident)
__device__ __forceinline__ void gsync(unsigned target) {
    __threadfence();
    __syncthreads();
    if (threadIdx.x == 0) {
        if (atomicAdd(&g_cnt, 1u) == NCSR - 1) {
            atomicExch(&g_cnt, 0u);
            __threadfence();
            atomicExch(&g_gen, target);
        } else {
            while (atomicAdd(&g_gen, 0u) < target) { }
        }
    }
    __syncthreads();
}

// ---------------- csr_mega: CSR build (blocks 0..97) || GEMM1 (blocks 98..147) ----------
extern "C" __global__ void __launch_bounds__(NT, 1)
csr_mega(const int* __restrict__ ei, const float* __restrict__ x,
         const float* __restrict__ W1) {
    __shared__ int s_wsum[32];
    __shared__ int s_prefix;
    __shared__ unsigned s_base;
    __shared__ __align__(16) __half sB[CH * 72];
    const int tid = threadIdx.x;
    const int bid = blockIdx.x;

    if (bid >= NCSR) {
        // ================= GEMM1 blocks: g_t = fp16(x) @ fp16(W1), fp32 out ==========
        for (int i = tid; i < CH * CH; i += NT)
            sB[(i >> 6) * 72 + (i & 63)] = __float2half(W1[i]);
        __syncthreads();

        const int lane = tid & 31;
        const int wg   = (bid - NCSR) * 32 + (tid >> 5);
        const int WSTR = (NB - NCSR) * 32;           // 1600 warps
        for (int t = wg; t < NTILES; t += WSTR) {
            // convert tile of x (16x64 fp32) -> g_a fp16
            const float2* src = (const float2*)(x + (size_t)t * 1024);
            __half2*      dst = (__half2*)(g_a + (size_t)t * 1024);
            for (int i = lane; i < 512; i += 32) {
                float2 f = src[i];
                dst[i] = __floats2half2_rn(f.x, f.y);
            }
            __threadfence_block();
            __syncwarp();

            wmma::fragment<wmma::accumulator, 16, 16, 16, float> acc[4];
#pragma unroll
            for (int j = 0; j < 4; j++) wmma::fill_fragment(acc[j], 0.f);
#pragma unroll
            for (int k = 0; k < 4; k++) {
                wmma::fragment<wmma::matrix_a, 16, 16, 16, __half, wmma::row_major> af;
                wmma::load_matrix_sync(af, g_a + (size_t)t * 1024 + k * 16, 64);
#pragma unroll
                for (int j = 0; j < 4; j++) {
                    wmma::fragment<wmma::matrix_b, 16, 16, 16, __half, wmma::row_major> bf;
                    wmma::load_matrix_sync(bf, sB + k * 16 * 72 + j * 16, 72);
                    wmma::mma_sync(acc[j], af, bf, acc[j]);
                }
            }
#pragma unroll
            for (int j = 0; j < 4; j++)
                wmma::store_matrix_sync(g_t + (size_t)t * 1024 + j * 16, acc[j], 64,
                                        wmma::mem_row_major);
        }
        return;
    }

    // ================= CSR blocks =================
    const int gt = bid * NT + tid;
    const int GS = NCSR * NT;

    if (tid == 0) s_base = atomicAdd(&g_gen, 0u);
    __syncthreads();
    const unsigned base = s_base;

    // P0: zero degrees
    for (int i = gt; i < NN; i += GS) g_deg[i] = 0;
    gsync(base + 1);

    // P1: count
    for (int e4 = gt; e4 < NE / 4; e4 += GS) {
        int4 c = *(const int4*)&ei[NE + e4 * 4];
        atomicAdd(&g_deg[c.x], 1);
        atomicAdd(&g_deg[c.y], 1);
        atomicAdd(&g_deg[c.z], 1);
        atomicAdd(&g_deg[c.w], 1);
    }
    gsync(base + 2);

    // P2: per-block scan of 8-padded degrees over contiguous chunk
    int node = bid * CHUNKC + tid;
    int deg  = (tid < CHUNKC && node < NN) ? g_deg[node] : 0;
    int v    = (deg + 7) & ~7;
    {
        int lane = tid & 31, wid = tid >> 5;
        int s = v;
#pragma unroll
        for (int d = 1; d < 32; d <<= 1) {
            int n = __shfl_up_sync(0xffffffffu, s, d);
            if (lane >= d) s += n;
        }
        if (lane == 31) s_wsum[wid] = s;
        __syncthreads();
        if (wid == 0) {
            int t = s_wsum[lane];
#pragma unroll
            for (int d = 1; d < 32; d <<= 1) {
                int n = __shfl_up_sync(0xffffffffu, t, d);
                if (lane >= d) t += n;
            }
            s_wsum[lane] = t;
        }
        __syncthreads();
        int warpExcl = (wid > 0) ? s_wsum[wid - 1] : 0;
        if (tid < CHUNKC && node < NN) g_off[node] = warpExcl + (s - v);
        if (tid == 0) g_bsums[bid] = s_wsum[31];
        gsync(base + 3);

        // P3: block-base prefix + finalize offsets/cursors/dinv + pad slots (0, 0.0f)
        if (tid < 32) {
            int sum = 0;
            for (int j = tid; j < bid; j += 32) sum += g_bsums[j];
#pragma unroll
            for (int d = 16; d; d >>= 1) sum += __shfl_xor_sync(0xffffffffu, sum, d);
            if (tid == 0) s_prefix = sum;
        }
        __syncthreads();
        if (tid < CHUNKC && node < NN) {
            int o = g_off[node] + s_prefix;
            g_off[node] = o;
            g_cur[node] = o;
            g_dinv[node] = rsqrtf((float)(deg + 1));
            for (int j = deg; j < v; j++) g_rw[o + j] = make_int2(0, 0);  // weight 0
        }
    }
    gsync(base + 4);

    // P4: fill real edges with (src, dinv[src])
    for (int e4 = gt; e4 < NE / 4; e4 += GS) {
        int4 r = *(const int4*)&ei[e4 * 4];
        int4 c = *(const int4*)&ei[NE + e4 * 4];
        g_rw[atomicAdd(&g_cur[c.x], 1)] = make_int2(r.x, __float_as_int(g_dinv[r.x]));
        g_rw[atomicAdd(&g_cur[c.y], 1)] = make_int2(r.y, __float_as_int(g_dinv[r.y]));
        g_rw[atomicAdd(&g_cur[c.z], 1)] = make_int2(r.z, __float_as_int(g_dinv[r.z]));
        g_rw[atomicAdd(&g_cur[c.w], 1)] = make_int2(r.w, __float_as_int(g_dinv[r.w]));
    }
}

// ---------------- GEMM2: g_t = g_a @ fp16(W2), A fragments direct from global ----------
__global__ void __launch_bounds__(256) k_gemm64(const float* __restrict__ W) {
    __shared__ __align__(16) __half sB[CH * 72];
    const int tid = threadIdx.x;
    for (int i = tid; i < CH * CH; i += 256)
        sB[(i >> 6) * 72 + (i & 63)] = __float2half(W[i]);
    __syncthreads();

    const int wg   = blockIdx.x * 8 + (tid >> 5);
    const int WSTR = gridDim.x * 8;
    for (int t = wg; t < NTILES; t += WSTR) {
        wmma::fragment<wmma::accumulator, 16, 16, 16, float> acc[4];
#pragma unroll
        for (int j = 0; j < 4; j++) wmma::fill_fragment(acc[j], 0.f);
#pragma unroll
        for (int k = 0; k < 4; k++) {
            wmma::fragment<wmma::matrix_a, 16, 16, 16, __half, wmma::row_major> af;
            wmma::load_matrix_sync(af, g_a + (size_t)t * 1024 + k * 16, 64);
#pragma unroll
            for (int j = 0; j < 4; j++) {
                wmma::fragment<wmma::matrix_b, 16, 16, 16, __half, wmma::row_major> bf;
                wmma::load_matrix_sync(bf, sB + k * 16 * 72 + j * 16, 72);
                wmma::mma_sync(acc[j], af, bf, acc[j]);
            }
        }
#pragma unroll
        for (int j = 0; j < 4; j++)
            wmma::store_matrix_sync(g_t + (size_t)t * 1024 + j * 16, acc[j], 64,
                                    wmma::mem_row_major);
    }
}

// ---------------- head: out = g_a @ fp16(Wlin) + blin (bias via accumulator init) ------
__global__ void __launch_bounds__(256) k_head(const float* __restrict__ W,
                                              const float* __restrict__ bias,
                                              float* __restrict__ outp) {
    __shared__ __align__(16) __half sB[CH * 40];
    __shared__ __align__(16) float  sBias[16 * OUTC];
    const int tid = threadIdx.x;
    for (int i = tid; i < CH * OUTC; i += 256)
        sB[(i / OUTC) * 40 + (i % OUTC)] = __float2half(W[i]);
    for (int i = tid; i < 16 * OUTC; i += 256) sBias[i] = bias[i & 31];
    __syncthreads();

    const int wg   = blockIdx.x * 8 + (tid >> 5);
    const int WSTR = gridDim.x * 8;
    for (int t = wg; t < NTILES; t += WSTR) {
        wmma::fragment<wmma::accumulator, 16, 16, 16, float> acc[2];
#pragma unroll
        for (int j = 0; j < 2; j++)
            wmma::load_matrix_sync(acc[j], sBias + j * 16, OUTC, wmma::mem_row_major);
#pragma unroll
        for (int k = 0; k < 4; k++) {
            wmma::fragment<wmma::matrix_a, 16, 16, 16, __half, wmma::row_major> af;
            wmma::load_matrix_sync(af, g_a + (size_t)t * 1024 + k * 16, 64);
#pragma unroll
            for (int j = 0; j < 2; j++) {
                wmma::fragment<wmma::matrix_b, 16, 16, 16, __half, wmma::row_major> bf;
                wmma::load_matrix_sync(bf, sB + k * 16 * 40 + j * 16, 40);
                wmma::mma_sync(acc[j], af, bf, acc[j]);
            }
        }
#pragma unroll
        for (int j = 0; j < 2; j++)
            wmma::store_matrix_sync(outp + (size_t)t * 16 * OUTC + j * 16, acc[j], OUTC,
                                    wmma::mem_row_major);
    }
}

// ---------------- agg: one warp per node; weighted fp32 gathers; fp16 out to g_a -------
// g_a[t] = fp16( relu( dinv[t]*sum_e w_e*g_t[r_e] + dinv[t]^2*g_t[t] + bias ) )
__global__ void k_agg(const float* __restrict__ bias) {
    int gw   = (blockIdx.x * blockDim.x + threadIdx.x) >> 5;
    int lane = threadIdx.x & 31;
    if (gw >= NN) return;

    int start = g_off[gw];
    int pcnt  = (g_deg[gw] + 7) & ~7;        // 8-padded; pads are (0, w=0)
    const float2* hp = (const float2*)g_t;

    float2 s0 = make_float2(0.f, 0.f), s1 = s0, s2 = s0, s3 = s0;

    if (pcnt > 0) {
        const int4* rw4 = (const int4*)&g_rw[start];   // 2 edges per int4
        int nq = pcnt >> 1;                             // int4 count
        int4 i0 = rw4[0], i1 = rw4[1], i2 = rw4[2], i3 = rw4[3];
        float2 v0 = hp[i0.x * 32 + lane], v1 = hp[i0.z * 32 + lane];
        float2 v2 = hp[i1.x * 32 + lane], v3 = hp[i1.z * 32 + lane];
        float2 v4 = hp[i2.x * 32 + lane], v5 = hp[i2.z * 32 + lane];
        float2 v6 = hp[i3.x * 32 + lane], v7 = hp[i3.z * 32 + lane];

        for (int q = 4; q < nq; q += 4) {
            int4 n0 = rw4[q], n1 = rw4[q + 1], n2 = rw4[q + 2], n3 = rw4[q + 3];
            float2 u0 = hp[n0.x * 32 + lane], u1 = hp[n0.z * 32 + lane];
            float2 u2 = hp[n1.x * 32 + lane], u3 = hp[n1.z * 32 + lane];
            float2 u4 = hp[n2.x * 32 + lane], u5 = hp[n2.z * 32 + lane];
            float2 u6 = hp[n3.x * 32 + lane], u7 = hp[n3.z * 32 + lane];
            float w0 = __int_as_float(i0.y), w1 = __int_as_float(i0.w);
            float w2 = __int_as_float(i1.y), w3 = __int_as_float(i1.w);
            float w4 = __int_as_float(i2.y), w5 = __int_as_float(i2.w);
            float w6 = __int_as_float(i3.y), w7 = __int_as_float(i3.w);
            s0.x = fmaf(w0, v0.x, s0.x); s0.y = fmaf(w0, v0.y, s0.y);
            s1.x = fmaf(w1, v1.x, s1.x); s1.y = fmaf(w1, v1.y, s1.y);
            s2.x = fmaf(w2, v2.x, s2.x); s2.y = fmaf(w2, v2.y, s2.y);
            s3.x = fmaf(w3, v3.x, s3.x); s3.y = fmaf(w3, v3.y, s3.y);
            s0.x = fmaf(w4, v4.x, s0.x); s0.y = fmaf(w4, v4.y, s0.y);
            s1.x = fmaf(w5, v5.x, s1.x); s1.y = fmaf(w5, v5.y, s1.y);
            s2.x = fmaf(w6, v6.x, s2.x); s2.y = fmaf(w6, v6.y, s2.y);
            s3.x = fmaf(w7, v7.x, s3.x); s3.y = fmaf(w7, v7.y, s3.y);
            i0 = n0; i1 = n1; i2 = n2; i3 = n3;
            v0 = u0; v1 = u1; v2 = u2; v3 = u3;
            v4 = u4; v5 = u5; v6 = u6; v7 = u7;
        }
        float w0 = __int_as_float(i0.y), w1 = __int_as_float(i0.w);
        float w2 = __int_as_float(i1.y), w3 = __int_as_float(i1.w);
        float w4 = __int_as_float(i2.y), w5 = __int_as_float(i2.w);
        float w6 = __int_as_float(i3.y), w7 = __int_as_float(i3.w);
        s0.x = fmaf(w0, v0.x, s0.x); s0.y = fmaf(w0, v0.y, s0.y);
        s1.x = fmaf(w1, v1.x, s1.x); s1.y = fmaf(w1, v1.y, s1.y);
        s2.x = fmaf(w2, v2.x, s2.x); s2.y = fmaf(w2, v2.y, s2.y);
        s3.x = fmaf(w3, v3.x, s3.x); s3.y = fmaf(w3, v3.y, s3.y);
        s0.x = fmaf(w4, v4.x, s0.x); s0.y = fmaf(w4, v4.y, s0.y);
        s1.x = fmaf(w5, v5.x, s1.x); s1.y = fmaf(w5, v5.y, s1.y);
        s2.x = fmaf(w6, v6.x, s2.x); s2.y = fmaf(w6, v6.y, s2.y);
        s3.x = fmaf(w7, v7.x, s3.x); s3.y = fmaf(w7, v7.y, s3.y);
    }

    float ax = (s0.x + s1.x) + (s2.x + s3.x);
    float ay = (s0.y + s1.y) + (s2.y + s3.y);

    float dt = g_dinv[gw];
    float2 sv = hp[gw * 32 + lane];
    float2 bb = ((const float2*)bias)[lane];
    float dt2 = dt * dt;
    float ox = fmaxf(dt * ax + dt2 * sv.x + bb.x, 0.f);
    float oy = fmaxf(dt * ay + dt2 * sv.y + bb.y, 0.f);
    ((__half2*)g_a)[gw * 32 + lane] = __floats2half2_rn(ox, oy);
}

// ---------------- launch ----------------
extern "C" void kernel_launch(void* const* d_in, const int* in_sizes, int n_in,
                              void* d_out, int out_size) {
    const float* x    = (const float*)d_in[0];
    const int*   ei   = (const int*)d_in[1];
    const float* W1   = (const float*)d_in[2];
    const float* b1   = (const float*)d_in[3];
    const float* W2   = (const float*)d_in[4];
    const float* b2   = (const float*)d_in[5];
    const float* Wlin = (const float*)d_in[6];
    const float* blin = (const float*)d_in[7];
    float* out = (float*)d_out;

    // 1: CSR build || GEMM1  (block-specialized, grid-synced among CSR blocks)
    csr_mega<<<NB, NT>>>(ei, x, W1);
    // 2: agg layer 1 -> g_a (fp16 h1)
    k_agg<<<(NN + 7) / 8, 256>>>(b1);
    // 3: GEMM2: g_a -> g_t (fp32)
    k_gemm64<<<296, 256>>>(W2);
    // 4: agg layer 2 -> g_a (fp16 h2)   <- profiled slot
    k_agg<<<(NN + 7) / 8, 256>>>(b2);
    // 5: head: g_a -> out (fp32 + bias)
    k_head<<<296, 256>>>(Wlin, blin, out);
}

// round 16
// speedup vs baseline: 1.0453x; 1.0453x over previous
#include <cuda_runtime.h>
#include <cuda_fp16.h>
#include <mma.h>

using namespace nvcuda;

#define NN 100000
#define NE 1600000
#define CH 64
#define OUTC 32
#define NB 148
#define NT 1024
#define CHUNK 676                        // ceil(NN / NB)
#define NTILES (NN / 16)                 // 6250 exact row tiles
#define NR (NE + 8 * NN + 16)            // 8-padded segment capacity

// ---------------- device scratch ----------------
__device__ int    g_deg[NN];
__device__ int    g_off[NN];
__device__ int    g_cur[NN];
__device__ float  g_dinv[NN];
__device__ int    g_bsums[NB];
__device__ __align__(16) int    g_r[NR];            // src rows sorted by target; pads -> row NN
__device__ __align__(16) __half g_a[NN * CH];       // GEMM A operand (fp16, dinv-prescaled)
__device__ __align__(16) __half g_t[(NN + 1) * CH]; // GEMM out / agg gather src; row NN = zeros
__device__ unsigned g_cnt;
__device__ unsigned g_gen;                           // monotonic barrier generation

// software grid barrier (all NB blocks co-resident)
__device__ __forceinline__ void gsync(unsigned target) {
    __threadfence();
    __syncthreads();
    if (threadIdx.x == 0) {
        if (atomicAdd(&g_cnt, 1u) == NB - 1) {
            atomicExch(&g_cnt, 0u);
            __threadfence();
            atomicExch(&g_gen, target);
        } else {
            while (atomicAdd(&g_gen, 0u) < target) { }
        }
    }
    __syncthreads();
}

// ---------------- CSR build + input conversion: one grid-synced kernel ----------------
extern "C" __global__ void __launch_bounds__(NT, 1)
csr_mega(const int* __restrict__ ei, const float* __restrict__ x) {
    __shared__ int s_wsum[32];
    __shared__ int s_prefix;
    __shared__ unsigned s_base;
    const int tid = threadIdx.x;
    const int bid = blockIdx.x;
    const int gt  = bid * NT + tid;
    const int GS  = NB * NT;

    if (tid == 0) s_base = atomicAdd(&g_gen, 0u);
    __syncthreads();
    const unsigned base = s_base;

    // P0: zero degrees
    for (int i = gt; i < NN; i += GS) g_deg[i] = 0;
    gsync(base + 1);

    // P1: count
    for (int e4 = gt; e4 < NE / 4; e4 += GS) {
        int4 c = *(const int4*)&ei[NE + e4 * 4];
        atomicAdd(&g_deg[c.x], 1);
        atomicAdd(&g_deg[c.y], 1);
        atomicAdd(&g_deg[c.z], 1);
        atomicAdd(&g_deg[c.w], 1);
    }
    gsync(base + 2);

    // P2: per-block scan of 8-padded degrees over contiguous chunk
    int node = bid * CHUNK + tid;
    int deg  = (tid < CHUNK && node < NN) ? g_deg[node] : 0;
    int v    = (deg + 7) & ~7;
    {
        int lane = tid & 31, wid = tid >> 5;
        int s = v;
#pragma unroll
        for (int d = 1; d < 32; d <<= 1) {
            int n = __shfl_up_sync(0xffffffffu, s, d);
            if (lane >= d) s += n;
        }
        if (lane == 31) s_wsum[wid] = s;
        __syncthreads();
        if (wid == 0) {
            int t = s_wsum[lane];
#pragma unroll
            for (int d = 1; d < 32; d <<= 1) {
                int n = __shfl_up_sync(0xffffffffu, t, d);
                if (lane >= d) t += n;
            }
            s_wsum[lane] = t;
        }
        __syncthreads();
        int warpExcl = (wid > 0) ? s_wsum[wid - 1] : 0;
        if (tid < CHUNK && node < NN) g_off[node] = warpExcl + (s - v);
        if (tid == 0) g_bsums[bid] = s_wsum[31];
        gsync(base + 3);

        // P3: block-base prefix + finalize offsets/cursors/dinv + pad slots -> zero row
        if (tid < 32) {
            int sum = 0;
            for (int j = tid; j < bid; j += 32) sum += g_bsums[j];
#pragma unroll
            for (int d = 16; d; d >>= 1) sum += __shfl_xor_sync(0xffffffffu, sum, d);
            if (tid == 0) s_prefix = sum;
        }
        __syncthreads();
        if (tid < CHUNK && node < NN) {
            int o = g_off[node] + s_prefix;
            g_off[node] = o;
            g_cur[node] = o;
            g_dinv[node] = rsqrtf((float)(deg + 1));
            for (int j = deg; j < v; j++) g_r[o + j] = NN;   // pad -> zero row
        }
    }
    gsync(base + 4);

    // P4a: fill real edges
    for (int e4 = gt; e4 < NE / 4; e4 += GS) {
        int4 r = *(const int4*)&ei[e4 * 4];
        int4 c = *(const int4*)&ei[NE + e4 * 4];
        g_r[atomicAdd(&g_cur[c.x], 1)] = r.x;
        g_r[atomicAdd(&g_cur[c.y], 1)] = r.y;
        g_r[atomicAdd(&g_cur[c.z], 1)] = r.z;
        g_r[atomicAdd(&g_cur[c.w], 1)] = r.w;
    }
    // P4b: g_a = fp16(dinv ⊙ x)   (dinv visible since barrier base+4)
    {
        const float2* xp = (const float2*)x;
        __half2* ap = (__half2*)g_a;
        for (int i = gt; i < NN * 32; i += GS) {
            float s = g_dinv[i >> 5];
            float2 f = xp[i];
            ap[i] = __floats2half2_rn(f.x * s, f.y * s);
        }
    }
}

// ---------------- GEMM (64-wide): g_t = g_a @ fp16(W); A direct from global; fp16 out ---
// 8 warps/block, one 16-row tile per warp; per-warp private fp32 smem stage for convert.
__global__ void __launch_bounds__(256) k_gemm64(const float* __restrict__ W) {
    __shared__ __align__(16) __half sB[CH * 72];            // 9216 B
    __shared__ __align__(16) float  sC[8][16 * 64];         // 32 KB, warp-private slabs
    const int tid  = threadIdx.x;
    const int wid  = tid >> 5;
    const int lane = tid & 31;

    for (int i = tid; i < CH * CH; i += 256)
        sB[(i >> 6) * 72 + (i & 63)] = __float2half(W[i]);
    __syncthreads();

    const int t = blockIdx.x * 8 + wid;
    if (t >= NTILES) return;

    wmma::fragment<wmma::accumulator, 16, 16, 16, float> acc[4];
#pragma unroll
    for (int j = 0; j < 4; j++) wmma::fill_fragment(acc[j], 0.f);
#pragma unroll
    for (int k = 0; k < 4; k++) {
        wmma::fragment<wmma::matrix_a, 16, 16, 16, __half, wmma::row_major> af;
        wmma::load_matrix_sync(af, g_a + (size_t)t * 1024 + k * 16, 64);
#pragma unroll
        for (int j = 0; j < 4; j++) {
            wmma::fragment<wmma::matrix_b, 16, 16, 16, __half, wmma::row_major> bf;
            wmma::load_matrix_sync(bf, sB + k * 16 * 72 + j * 16, 72);
            wmma::mma_sync(acc[j], af, bf, acc[j]);
        }
    }

    float* myC = sC[wid];
#pragma unroll
    for (int j = 0; j < 4; j++)
        wmma::store_matrix_sync(myC + j * 16, acc[j], 64, wmma::mem_row_major);
    __syncwarp();

    // convert 16x64 fp32 -> fp16; 2 lanes per row, 32 floats each
    {
        int r   = lane >> 1;
        int off = (lane & 1) * 32;
        const float* src = myC + r * 64 + off;
        __half2 hv[16];
#pragma unroll
        for (int j = 0; j < 16; j++) hv[j] = __floats2half2_rn(src[2 * j], src[2 * j + 1]);
        uint4* dst = (uint4*)(g_t + ((size_t)t * 16 + r) * 64 + off);
#pragma unroll
        for (int j = 0; j < 4; j++) dst[j] = ((uint4*)hv)[j];
    }
}

// ---------------- head: out = g_a @ fp16(Wlin) + blin (bias via accumulator init) ------
__global__ void __launch_bounds__(256) k_head(const float* __restrict__ W,
                                              const float* __restrict__ bias,
                                              float* __restrict__ outp) {
    __shared__ __align__(16) __half sB[CH * 40];
    __shared__ __align__(16) float  sBias[16 * OUTC];
    const int tid = threadIdx.x;
    for (int i = tid; i < CH * OUTC; i += 256)
        sB[(i / OUTC) * 40 + (i % OUTC)] = __float2half(W[i]);
    for (int i = tid; i < 16 * OUTC; i += 256) sBias[i] = bias[i & 31];
    __syncthreads();

    const int t = blockIdx.x * 8 + (tid >> 5);
    if (t >= NTILES) return;

    wmma::fragment<wmma::accumulator, 16, 16, 16, float> acc[2];
#pragma unroll
    for (int j = 0; j < 2; j++)
        wmma::load_matrix_sync(acc[j], sBias + j * 16, OUTC, wmma::mem_row_major);
#pragma unroll
    for (int k = 0; k < 4; k++) {
        wmma::fragment<wmma::matrix_a, 16, 16, 16, __half, wmma::row_major> af;
        wmma::load_matrix_sync(af, g_a + (size_t)t * 1024 + k * 16, 64);
#pragma unroll
        for (int j = 0; j < 2; j++) {
            wmma::fragment<wmma::matrix_b, 16, 16, 16, __half, wmma::row_major> bf;
            wmma::load_matrix_sync(bf, sB + k * 16 * 40 + j * 16, 40);
            wmma::mma_sync(acc[j], af, bf, acc[j]);
        }
    }
#pragma unroll
    for (int j = 0; j < 2; j++)
        wmma::store_matrix_sync(outp + (size_t)t * 16 * OUTC + j * 16, acc[j], OUTC,
                                wmma::mem_row_major);
}

// ---------------- agg: one warp per node; branch-free 8-wide pipelined fp16 gathers ----
// h = relu( dinv[t]*(sum_nbr g_t[r] + g_t[t]) + bias );  g_a = fp16(SCALE_OUT ? dt*h : h)
template<bool SCALE_OUT>
__global__ void k_agg(const float* __restrict__ bias) {
    int gw   = (blockIdx.x * blockDim.x + threadIdx.x) >> 5;
    int lane = threadIdx.x & 31;
    if (gw >= NN) return;

    int start = g_off[gw];
    int pcnt  = (g_deg[gw] + 7) & ~7;        // 8-padded; pads hit zero row
    int endp  = start + pcnt;
    const __half2* hp = (const __half2*)g_t;

    float2 s0 = make_float2(0.f, 0.f), s1 = s0, s2 = s0, s3 = s0;

    if (pcnt > 0) {
        int4 ia = *(const int4*)&g_r[start];
        int4 ib = *(const int4*)&g_r[start + 4];
        __half2 g0 = hp[ia.x * 32 + lane], g1 = hp[ia.y * 32 + lane];
        __half2 g2 = hp[ia.z * 32 + lane], g3 = hp[ia.w * 32 + lane];
        __half2 g4 = hp[ib.x * 32 + lane], g5 = hp[ib.y * 32 + lane];
        __half2 g6 = hp[ib.z * 32 + lane], g7 = hp[ib.w * 32 + lane];

        for (int e = start + 8; e < endp; e += 8) {
            int4 na = *(const int4*)&g_r[e];
            int4 nb = *(const int4*)&g_r[e + 4];
            __half2 n0 = hp[na.x * 32 + lane], n1 = hp[na.y * 32 + lane];
            __half2 n2 = hp[na.z * 32 + lane], n3 = hp[na.w * 32 + lane];
            __half2 n4 = hp[nb.x * 32 + lane], n5 = hp[nb.y * 32 + lane];
            __half2 n6 = hp[nb.z * 32 + lane], n7 = hp[nb.w * 32 + lane];
            { float2 v = __half22float2(g0); s0.x += v.x; s0.y += v.y; }
            { float2 v = __half22float2(g1); s1.x += v.x; s1.y += v.y; }
            { float2 v = __half22float2(g2); s2.x += v.x; s2.y += v.y; }
            { float2 v = __half22float2(g3); s3.x += v.x; s3.y += v.y; }
            { float2 v = __half22float2(g4); s0.x += v.x; s0.y += v.y; }
            { float2 v = __half22float2(g5); s1.x += v.x; s1.y += v.y; }
            { float2 v = __half22float2(g6); s2.x += v.x; s2.y += v.y; }
            { float2 v = __half22float2(g7); s3.x += v.x; s3.y += v.y; }
            g0 = n0; g1 = n1; g2 = n2; g3 = n3;
            g4 = n4; g5 = n5; g6 = n6; g7 = n7;
        }
        { float2 v = __half22float2(g0); s0.x += v.x; s0.y += v.y; }
        { float2 v = __half22float2(g1); s1.x += v.x; s1.y += v.y; }
        { float2 v = __half22float2(g2); s2.x += v.x; s2.y += v.y; }
        { float2 v = __half22float2(g3); s3.x += v.x; s3.y += v.y; }
        { float2 v = __half22float2(g4); s0.x += v.x; s0.y += v.y; }
        { float2 v = __half22float2(g5); s1.x += v.x; s1.y += v.y; }
        { float2 v = __half22float2(g6); s2.x += v.x; s2.y += v.y; }
        { float2 v = __half22float2(g7); s3.x += v.x; s3.y += v.y; }
    }

    float ax = (s0.x + s1.x) + (s2.x + s3.x);
    float ay = (s0.y + s1.y) + (s2.y + s3.y);

    float dt = g_dinv[gw];
    float2 sv = __half22float2(hp[gw * 32 + lane]);
    float2 bb = ((const float2*)bias)[lane];
    float ox = fmaxf(fmaf(dt, ax + sv.x, bb.x), 0.f);
    float oy = fmaxf(fmaf(dt, ay + sv.y, bb.y), 0.f);
    if (SCALE_OUT) { ox *= dt; oy *= dt; }
    ((__half2*)g_a)[gw * 32 + lane] = __floats2half2_rn(ox, oy);
}

// ---------------- launch ----------------
extern "C" void kernel_launch(void* const* d_in, const int* in_sizes, int n_in,
                              void* d_out, int out_size) {
    const float* x    = (const float*)d_in[0];
    const int*   ei   = (const int*)d_in[1];
    const float* W1   = (const float*)d_in[2];
    const float* b1   = (const float*)d_in[3];
    const float* W2   = (const float*)d_in[4];
    const float* b2   = (const float*)d_in[5];
    const float* Wlin = (const float*)d_in[6];
    const float* blin = (const float*)d_in[7];
    float* out = (float*)d_out;

    const int GGRID = (NTILES + 7) / 8;   // 782 blocks, 1 tile per warp

    // 1: CSR build + g_a = fp16(dinv⊙x)
    csr_mega<<<NB, NT>>>(ei, x);
    // 2: GEMM1: g_a -> g_t (fp16, prescaled)
    k_gemm64<<<GGRID, 256>>>(W1);
    // 3: agg layer 1 -> g_a (fp16, dt-scaled for next GEMM)
    k_agg<true><<<(NN + 7) / 8, 256>>>(b1);
    // 4: GEMM2: g_a -> g_t (fp16)   <- profiled slot
    k_gemm64<<<GGRID, 256>>>(W2);
    // 5: agg layer 2 -> g_a (fp16 h2)
    k_agg<false><<<(NN + 7) / 8, 256>>>(b2);
    // 6: head: g_a -> out (fp32 + bias)
    k_head<<<GGRID, 256>>>(Wlin, blin, out);
}

// round 17
// speedup vs baseline: 1.0927x; 1.0454x over previous
#include <cuda_runtime.h>
#include <cuda_fp16.h>
#include <mma.h>

using namespace nvcuda;

#define NN 100000
#define NE 1600000
#define CH 64
#define OUTC 32
#define NB 148
#define NT 1024
#define CHUNK 676                        // ceil(NN / NB)
#define NTILES (NN / 16)                 // 6250 exact tiles (16 rows each)
#define NR (NE + 8 * NN + 16)            // 8-padded segment capacity
#define ROWPAD 128                       // buffer overhang for 64-row GEMM1 blocks

// ---------------- device scratch ----------------
__device__ int    g_deg[NN];
__device__ int    g_off[NN];
__device__ int    g_cur[NN];
__device__ float  g_dinv[NN];
__device__ int    g_bsums[NB];
__device__ __align__(16) int    g_r[NR];                 // src rows sorted by target; pads -> row NN
__device__ __align__(16) __half g_a[(NN + ROWPAD) * CH]; // x (prescaled) -> GEMM1 in; GEMM2 out; rows>=NN stay 0
__device__ __align__(16) __half g_t[(NN + ROWPAD) * CH]; // GEMM1 out = agg1 gather src; rows>=NN stay 0
__device__ __align__(16) __half g_w2h[CH * CH];          // W2 fp16
__device__ __align__(16) __half g_wlh[CH * OUTC];        // Wlin fp16
__device__ unsigned g_cnt;
__device__ unsigned g_gen;                                // monotonic barrier generation

// software grid barrier (all NB blocks co-resident)
__device__ __forceinline__ void gsync(unsigned target) {
    __threadfence();
    __syncthreads();
    if (threadIdx.x == 0) {
        if (atomicAdd(&g_cnt, 1u) == NB - 1) {
            atomicExch(&g_cnt, 0u);
            __threadfence();
            atomicExch(&g_gen, target);
        } else {
            while (atomicAdd(&g_gen, 0u) < target) { }
        }
    }
    __syncthreads();
}

// ---------------- CSR build + input/weight conversion: one grid-synced kernel ----------
extern "C" __global__ void __launch_bounds__(NT, 1)
csr_mega(const int* __restrict__ ei, const float* __restrict__ x,
         const float* __restrict__ W2, const float* __restrict__ Wlin) {
    __shared__ int s_wsum[32];
    __shared__ int s_prefix;
    __shared__ unsigned s_base;
    const int tid = threadIdx.x;
    const int bid = blockIdx.x;
    const int gt  = bid * NT + tid;
    const int GS  = NB * NT;

    if (tid == 0) s_base = atomicAdd(&g_gen, 0u);
    __syncthreads();
    const unsigned base = s_base;

    // P0: zero degrees (+ blocks 1,2 convert W2/Wlin to fp16 globals)
    for (int i = gt; i < NN; i += GS) g_deg[i] = 0;
    if (bid == 1) for (int i = tid; i < CH * CH; i += NT) g_w2h[i] = __float2half(W2[i]);
    if (bid == 2) for (int i = tid; i < CH * OUTC; i += NT) g_wlh[i] = __float2half(Wlin[i]);
    gsync(base + 1);

    // P1: count
    for (int e4 = gt; e4 < NE / 4; e4 += GS) {
        int4 c = *(const int4*)&ei[NE + e4 * 4];
        atomicAdd(&g_deg[c.x], 1);
        atomicAdd(&g_deg[c.y], 1);
        atomicAdd(&g_deg[c.z], 1);
        atomicAdd(&g_deg[c.w], 1);
    }
    gsync(base + 2);

    // P2: per-block scan of 8-padded degrees over contiguous chunk
    int node = bid * CHUNK + tid;
    int deg  = (tid < CHUNK && node < NN) ? g_deg[node] : 0;
    int v    = (deg + 7) & ~7;
    {
        int lane = tid & 31, wid = tid >> 5;
        int s = v;
#pragma unroll
        for (int d = 1; d < 32; d <<= 1) {
            int n = __shfl_up_sync(0xffffffffu, s, d);
            if (lane >= d) s += n;
        }
        if (lane == 31) s_wsum[wid] = s;
        __syncthreads();
        if (wid == 0) {
            int t = s_wsum[lane];
#pragma unroll
            for (int d = 1; d < 32; d <<= 1) {
                int n = __shfl_up_sync(0xffffffffu, t, d);
                if (lane >= d) t += n;
            }
            s_wsum[lane] = t;
        }
        __syncthreads();
        int warpExcl = (wid > 0) ? s_wsum[wid - 1] : 0;
        if (tid < CHUNK && node < NN) g_off[node] = warpExcl + (s - v);
        if (tid == 0) g_bsums[bid] = s_wsum[31];
        gsync(base + 3);

        // P3: block-base prefix + finalize offsets/cursors/dinv + pad slots -> zero row
        if (tid < 32) {
            int sum = 0;
            for (int j = tid; j < bid; j += 32) sum += g_bsums[j];
#pragma unroll
            for (int d = 16; d; d >>= 1) sum += __shfl_xor_sync(0xffffffffu, sum, d);
            if (tid == 0) s_prefix = sum;
        }
        __syncthreads();
        if (tid < CHUNK && node < NN) {
            int o = g_off[node] + s_prefix;
            g_off[node] = o;
            g_cur[node] = o;
            g_dinv[node] = rsqrtf((float)(deg + 1));
            for (int j = deg; j < v; j++) g_r[o + j] = NN;   // pad -> zero row
        }
    }
    gsync(base + 4);

    // P4a: fill real edges
    for (int e4 = gt; e4 < NE / 4; e4 += GS) {
        int4 r = *(const int4*)&ei[e4 * 4];
        int4 c = *(const int4*)&ei[NE + e4 * 4];
        g_r[atomicAdd(&g_cur[c.x], 1)] = r.x;
        g_r[atomicAdd(&g_cur[c.y], 1)] = r.y;
        g_r[atomicAdd(&g_cur[c.z], 1)] = r.z;
        g_r[atomicAdd(&g_cur[c.w], 1)] = r.w;
    }
    // P4b: g_a = fp16(dinv ⊙ x)   (dinv visible since barrier base+4)
    {
        const float2* xp = (const float2*)x;
        __half2* ap = (__half2*)g_a;
        for (int i = gt; i < NN * 32; i += GS) {
            float s = g_dinv[i >> 5];
            float2 f = xp[i];
            ap[i] = __floats2half2_rn(f.x * s, f.y * s);
        }
    }
}

// ---------------- GEMM1: g_t = g_a @ fp16(W1); smem-staged A; fp16 out ----------------
// 128 threads (4 warps), 64 rows/block; A staged via coalesced LDG.128.
__global__ void __launch_bounds__(128) k_gemm1(const float* __restrict__ W) {
    __shared__ __align__(16) __half sA[64 * 72];     // 9216 B
    __shared__ __align__(16) __half sB[64 * 72];     // 9216 B
    __shared__ __align__(16) float  sC[4][16 * 64];  // 16384 B
    const int tid = threadIdx.x, wid = tid >> 5, lane = tid & 31;

    for (int i = tid; i < CH * CH; i += 128)
        sB[(i >> 6) * 72 + (i & 63)] = __float2half(W[i]);
    const int row0 = blockIdx.x * 64;
    {
        const uint4* src = (const uint4*)(g_a + (size_t)row0 * CH);   // 64 rows x 8 uint4
        uint4* dst = (uint4*)sA;                                      // 72 halves = 9 uint4/row
        for (int i = tid; i < 512; i += 128)
            dst[(i >> 3) * 9 + (i & 7)] = src[i];
    }
    __syncthreads();

    wmma::fragment<wmma::accumulator, 16, 16, 16, float> acc[4];
#pragma unroll
    for (int j = 0; j < 4; j++) wmma::fill_fragment(acc[j], 0.f);
#pragma unroll
    for (int k = 0; k < 4; k++) {
        wmma::fragment<wmma::matrix_a, 16, 16, 16, __half, wmma::row_major> af;
        wmma::load_matrix_sync(af, sA + wid * 16 * 72 + k * 16, 72);
#pragma unroll
        for (int j = 0; j < 4; j++) {
            wmma::fragment<wmma::matrix_b, 16, 16, 16, __half, wmma::row_major> bf;
            wmma::load_matrix_sync(bf, sB + k * 16 * 72 + j * 16, 72);
            wmma::mma_sync(acc[j], af, bf, acc[j]);
        }
    }
    float* myC = sC[wid];
#pragma unroll
    for (int j = 0; j < 4; j++)
        wmma::store_matrix_sync(myC + j * 16, acc[j], 64, wmma::mem_row_major);
    __syncwarp();
    {
        int r   = lane >> 1;
        int off = (lane & 1) * 32;
        const float* src = myC + r * 64 + off;
        __half2 hv[16];
#pragma unroll
        for (int j = 0; j < 16; j++) hv[j] = __floats2half2_rn(src[2 * j], src[2 * j + 1]);
        uint4* dst = (uint4*)(g_t + ((size_t)(row0 + wid * 16 + r)) * 64 + off);
#pragma unroll
        for (int j = 0; j < 4; j++) dst[j] = ((uint4*)hv)[j];
    }
}

// ---------------- per-warp aggregation core (branch-free 8-wide pipelined fp16 gathers)
// returns relu( dt*(sum_nbr src[r] + src[node]) + bias ) for this lane's 2 channels
__device__ __forceinline__ float2 agg_node(const __half* __restrict__ srcbuf, int node,
                                           int lane, const float* __restrict__ bias) {
    int start = g_off[node];
    int pcnt  = (g_deg[node] + 7) & ~7;
    int endp  = start + pcnt;
    const __half2* hp = (const __half2*)srcbuf;

    float2 s0 = make_float2(0.f, 0.f), s1 = s0, s2 = s0, s3 = s0;
    if (pcnt > 0) {
        int4 ia = *(const int4*)&g_r[start];
        int4 ib = *(const int4*)&g_r[start + 4];
        __half2 g0 = hp[ia.x * 32 + lane], g1 = hp[ia.y * 32 + lane];
        __half2 g2 = hp[ia.z * 32 + lane], g3 = hp[ia.w * 32 + lane];
        __half2 g4 = hp[ib.x * 32 + lane], g5 = hp[ib.y * 32 + lane];
        __half2 g6 = hp[ib.z * 32 + lane], g7 = hp[ib.w * 32 + lane];
        for (int e = start + 8; e < endp; e += 8) {
            int4 na = *(const int4*)&g_r[e];
            int4 nb = *(const int4*)&g_r[e + 4];
            __half2 n0 = hp[na.x * 32 + lane], n1 = hp[na.y * 32 + lane];
            __half2 n2 = hp[na.z * 32 + lane], n3 = hp[na.w * 32 + lane];
            __half2 n4 = hp[nb.x * 32 + lane], n5 = hp[nb.y * 32 + lane];
            __half2 n6 = hp[nb.z * 32 + lane], n7 = hp[nb.w * 32 + lane];
            { float2 v = __half22float2(g0); s0.x += v.x; s0.y += v.y; }
            { float2 v = __half22float2(g1); s1.x += v.x; s1.y += v.y; }
            { float2 v = __half22float2(g2); s2.x += v.x; s2.y += v.y; }
            { float2 v = __half22float2(g3); s3.x += v.x; s3.y += v.y; }
            { float2 v = __half22float2(g4); s0.x += v.x; s0.y += v.y; }
            { float2 v = __half22float2(g5); s1.x += v.x; s1.y += v.y; }
            { float2 v = __half22float2(g6); s2.x += v.x; s2.y += v.y; }
            { float2 v = __half22float2(g7); s3.x += v.x; s3.y += v.y; }
            g0 = n0; g1 = n1; g2 = n2; g3 = n3;
            g4 = n4; g5 = n5; g6 = n6; g7 = n7;
        }
        { float2 v = __half22float2(g0); s0.x += v.x; s0.y += v.y; }
        { float2 v = __half22float2(g1); s1.x += v.x; s1.y += v.y; }
        { float2 v = __half22float2(g2); s2.x += v.x; s2.y += v.y; }
        { float2 v = __half22float2(g3); s3.x += v.x; s3.y += v.y; }
        { float2 v = __half22float2(g4); s0.x += v.x; s0.y += v.y; }
        { float2 v = __half22float2(g5); s1.x += v.x; s1.y += v.y; }
        { float2 v = __half22float2(g6); s2.x += v.x; s2.y += v.y; }
        { float2 v = __half22float2(g7); s3.x += v.x; s3.y += v.y; }
    }
    float ax = (s0.x + s1.x) + (s2.x + s3.x);
    float ay = (s0.y + s1.y) + (s2.y + s3.y);
    float dt = g_dinv[node];
    float2 sv = __half22float2(hp[node * 32 + lane]);
    float2 bb = ((const float2*)bias)[lane];
    float2 r;
    r.x = fmaxf(fmaf(dt, ax + sv.x, bb.x), 0.f);
    r.y = fmaxf(fmaf(dt, ay + sv.y, bb.y), 0.f);
    return r;
}

// ---------------- fused1: agg layer-1 (gather g_t) + GEMM2 -> g_a ----------------------
// 512 threads = 16 warps = 16 nodes = one GEMM row-tile.
__global__ void __launch_bounds__(512) k_fused1(const float* __restrict__ bias) {
    __shared__ __align__(16) __half sA[16 * 72];    // prescaled h1 rows
    __shared__ __align__(16) __half sB[64 * 72];    // W2 fp16
    __shared__ __align__(16) float  sC[16 * 64];    // GEMM2 fp32 out
    const int tid = threadIdx.x, wid = tid >> 5, lane = tid & 31;
    const int t = blockIdx.x;

    // load W2h (independent of agg; latency hidden behind gathers)
    for (int i = tid; i < CH * CH; i += 512)
        sB[(i >> 6) * 72 + (i & 63)] = g_w2h[i];

    // aggregate: node per warp; prescale by dinv for GEMM2 input
    {
        int node = t * 16 + wid;
        float2 h = agg_node(g_t, node, lane, bias);
        float dt = g_dinv[node];
        ((__half2*)(sA + wid * 72))[lane] = __floats2half2_rn(h.x * dt, h.y * dt);
    }
    __syncthreads();

    // GEMM2: 16x64 @ 64x64, 4 warps each take one 16-col group
    if (wid < 4) {
        wmma::fragment<wmma::accumulator, 16, 16, 16, float> acc;
        wmma::fill_fragment(acc, 0.f);
#pragma unroll
        for (int k = 0; k < 4; k++) {
            wmma::fragment<wmma::matrix_a, 16, 16, 16, __half, wmma::row_major> af;
            wmma::load_matrix_sync(af, sA + k * 16, 72);
            wmma::fragment<wmma::matrix_b, 16, 16, 16, __half, wmma::row_major> bf;
            wmma::load_matrix_sync(bf, sB + k * 16 * 72 + wid * 16, 72);
            wmma::mma_sync(acc, af, bf, acc);
        }
        wmma::store_matrix_sync(sC + wid * 16, acc, 64, wmma::mem_row_major);
    }
    __syncthreads();

    // convert 16x64 fp32 -> fp16 tile of g_a (coalesced half2 stores)
    {
        float2 f = ((const float2*)sC)[tid];
        ((__half2*)g_a)[(size_t)t * 512 + tid] = __floats2half2_rn(f.x, f.y);
    }
}

// ---------------- fused2: agg layer-2 (gather g_a) + linear head -> out ----------------
__global__ void __launch_bounds__(512) k_fused2(const float* __restrict__ bias,
                                                float* __restrict__ outp) {
    __shared__ __align__(16) __half sA[16 * 72];
    __shared__ __align__(16) __half sB[64 * 40];    // Wlin fp16 (pad 40)
    __shared__ __align__(16) float  sBias[16 * OUTC];
    const int tid = threadIdx.x, wid = tid >> 5, lane = tid & 31;
    const int t = blockIdx.x;

    for (int i = tid; i < CH * OUTC; i += 512)
        sB[(i >> 5) * 40 + (i & 31)] = g_wlh[i];
    if (tid < 16 * OUTC) sBias[tid] = bias[tid & 31];

    {
        int node = t * 16 + wid;
        float2 h = agg_node(g_a, node, lane, bias ? bias : bias);  // bias is b2 (agg bias)
        ((__half2*)(sA + wid * 72))[lane] = __floats2half2_rn(h.x, h.y);
    }
    __syncthreads();

    // head: 16x64 @ 64x32 + blin... wait: sBias must hold blin, bias param is b2.
    if (wid < 2) {
        wmma::fragment<wmma::accumulator, 16, 16, 16, float> acc;
        wmma::load_matrix_sync(acc, sBias + wid * 16, OUTC, wmma::mem_row_major);
#pragma unroll
        for (int k = 0; k < 4; k++) {
            wmma::fragment<wmma::matrix_a, 16, 16, 16, __half, wmma::row_major> af;
            wmma::load_matrix_sync(af, sA + k * 16, 72);
            wmma::fragment<wmma::matrix_b, 16, 16, 16, __half, wmma::row_major> bf;
            wmma::load_matrix_sync(bf, sB + k * 16 * 40 + wid * 16, 40);
            wmma::mma_sync(acc, af, bf, acc);
        }
        wmma::store_matrix_sync(outp + (size_t)t * 512 + wid * 16, acc, OUTC,
                                wmma::mem_row_major);
    }
}

// NOTE: k_fused2 needs BOTH b2 (agg bias) and blin (head bias) — fixed signature below.
__global__ void __launch_bounds__(512) k_fused2b(const float* __restrict__ b2,
                                                 const float* __restrict__ blin,
                                                 float* __restrict__ outp) {
    __shared__ __align__(16) __half sA[16 * 72];
    __shared__ __align__(16) __half sB[64 * 40];
    __shared__ __align__(16) float  sBias[16 * OUTC];
    const int tid = threadIdx.x, wid = tid >> 5, lane = tid & 31;
    const int t = blockIdx.x;

    for (int i = tid; i < CH * OUTC; i += 512)
        sB[(i >> 5) * 40 + (i & 31)] = g_wlh[i];
    if (tid < 16 * OUTC) sBias[tid] = blin[tid & 31];

    {
        int node = t * 16 + wid;
        float2 h = agg_node(g_a, node, lane, b2);
        ((__half2*)(sA + wid * 72))[lane] = __floats2half2_rn(h.x, h.y);
    }
    __syncthreads();

    if (wid < 2) {
        wmma::fragment<wmma::accumulator, 16, 16, 16, float> acc;
        wmma::load_matrix_sync(acc, sBias + wid * 16, OUTC, wmma::mem_row_major);
#pragma unroll
        for (int k = 0; k < 4; k++) {
            wmma::fragment<wmma::matrix_a, 16, 16, 16, __half, wmma::row_major> af;
            wmma::load_matrix_sync(af, sA + k * 16, 72);
            wmma::fragment<wmma::matrix_b, 16, 16, 16, __half, wmma::row_major> bf;
            wmma::load_matrix_sync(bf, sB + k * 16 * 40 + wid * 16, 40);
            wmma::mma_sync(acc, af, bf, acc);
        }
        wmma::store_matrix_sync(outp + (size_t)t * 512 + wid * 16, acc, OUTC,
                                wmma::mem_row_major);
    }
}

// ---------------- launch ----------------
extern "C" void kernel_launch(void* const* d_in, const int* in_sizes, int n_in,
                              void* d_out, int out_size) {
    const float* x    = (const float*)d_in[0];
    const int*   ei   = (const int*)d_in[1];
    const float* W1   = (const float*)d_in[2];
    const float* b1   = (const float*)d_in[3];
    const float* W2   = (const float*)d_in[4];
    const float* b2   = (const float*)d_in[5];
    const float* Wlin = (const float*)d_in[6];
    const float* blin = (const float*)d_in[7];
    float* out = (float*)d_out;

    // 1: CSR build + g_a = fp16(dinv⊙x) + W2/Wlin fp16 precompute
    csr_mega<<<NB, NT>>>(ei, x, W2, Wlin);
    // 2: GEMM1 (smem-staged): g_a -> g_t
    k_gemm1<<<(NN + 63) / 64, 128>>>(W1);
    // 3: fused agg1 + GEMM2: g_t -> g_a
    k_fused1<<<NTILES, 512>>>(b1);
    // 4: fused agg2 + head: g_a -> out   <- profiled slot
    k_fused2b<<<NTILES, 512>>>(b2, blin, out);
}